// round 13
// baseline (speedup 1.0000x reference)
#include <cuda_runtime.h>

#define NV 100000
#define NE 200000
#define NF 100000
#define N_EV 400000
#define N_FE 800000
#define N_FF 800000
#define WD 128
#define NDST_TOT (NE + NF + NF)
#define NEDGE_TOT (N_EV + N_FE + N_FF)

__device__ __align__(16) float g_xv[NV * WD];
__device__ __align__(16) float g_xe[NE * WD];
__device__ __align__(16) float g_max[NE * WD];
__device__ int g_cnt[NDST_TOT];
__device__ int g_ptr[NDST_TOT];
__device__ int g_cur[NDST_TOT];
__device__ int g_bsum[256];
__device__ int g_csr[NEDGE_TOT];
__device__ unsigned g_barcnt;
__device__ volatile unsigned g_bargen;

typedef unsigned long long u64;

__device__ __forceinline__ u64 pk2(float lo, float hi) {
    u64 r; asm("mov.b64 %0, {%1,%2};" : "=l"(r) : "f"(lo), "f"(hi)); return r;
}
__device__ __forceinline__ float2 upk2(u64 v) {
    float2 r; asm("mov.b64 {%0,%1}, %2;" : "=f"(r.x), "=f"(r.y) : "l"(v)); return r;
}
// Packed fp32x2 FMA: 2x FFMA rate on sm_103a (PTX-only form).
__device__ __forceinline__ u64 ffma2(u64 a, u64 b, u64 c) {
    u64 d; asm("fma.rn.f32x2 %0, %1, %2, %3;" : "=l"(d) : "l"(a), "l"(b), "l"(c)); return d;
}
__device__ __forceinline__ void cp16(unsigned dst, const void* src, int srcsz) {
    asm volatile("cp.async.cg.shared.global [%0], [%1], 16, %2;"
                 :: "r"(dst), "l"(src), "r"(srcsz));
}
#define CP_COMMIT() asm volatile("cp.async.commit_group;")
#define CP_WAIT1()  asm volatile("cp.async.wait_group 1;")
#define CP_WAIT0()  asm volatile("cp.async.wait_group 0;")

// ---------------- software global barrier ----------------
__device__ __forceinline__ void gbar() {
    __syncthreads();
    if (threadIdx.x == 0) {
        unsigned gen = g_bargen;
        __threadfence();
        if (atomicAdd(&g_barcnt, 1) == gridDim.x - 1) {
            g_barcnt = 0; __threadfence(); g_bargen = gen + 1;
        } else { while (g_bargen == gen) __nanosleep(64); }
        __threadfence();
    }
    __syncthreads();
}

__device__ __forceinline__ int block_scan_incl(int v, int* tot, int* swarp) {
    int lane = threadIdx.x & 31, wid = threadIdx.x >> 5;
    int s = v;
#pragma unroll
    for (int o = 1; o < 32; o <<= 1) { int t = __shfl_up_sync(~0u, s, o); if (lane >= o) s += t; }
    if (lane == 31) swarp[wid] = s;
    __syncthreads();
    if (wid == 0) {
        int w = swarp[lane];
#pragma unroll
        for (int o = 1; o < 32; o <<= 1) { int t = __shfl_up_sync(~0u, w, o); if (lane >= o) w += t; }
        swarp[lane] = w;
    }
    __syncthreads();
    int add = (wid > 0) ? swarp[wid - 1] : 0;
    *tot = swarp[31];
    int r = s + add;
    __syncthreads();
    return r;
}

// ---------------- build all 3 CSRs in ONE kernel ----------------
__global__ void __launch_bounds__(1024)
build_csr_all(const int* __restrict__ etv_v, const int* __restrict__ etv_e,
              const int* __restrict__ fte_e, const int* __restrict__ fte_f,
              const int* __restrict__ ftf_src, const int* __restrict__ ftf_dst)
{
    __shared__ int swarp[32];
    int gtid = blockIdx.x * 1024 + threadIdx.x, gs = gridDim.x * 1024;
    for (int i = gtid; i < NDST_TOT; i += gs) g_cnt[i] = 0;
    gbar();
    for (int e = gtid; e < N_EV; e += gs) atomicAdd(&g_cnt[__ldg(etv_e + e)], 1);
    for (int e = gtid; e < N_FE; e += gs) atomicAdd(&g_cnt[NE + __ldg(fte_f + e)], 1);
    for (int e = gtid; e < N_FF; e += gs) atomicAdd(&g_cnt[NE + NF + __ldg(ftf_dst + e)], 1);
    gbar();
    const int CHUNK = (NDST_TOT + gridDim.x - 1) / gridDim.x;
    int base = blockIdx.x * CHUNK, lim = min(base + CHUNK, NDST_TOT), carry = 0;
    for (int t = base; t < base + CHUNK; t += 1024) {
        int i = t + threadIdx.x;
        int v = (i < lim) ? g_cnt[i] : 0;
        int tot; int incl = block_scan_incl(v, &tot, swarp);
        if (i < lim) g_ptr[i] = carry + incl - v;
        carry += tot;
    }
    if (threadIdx.x == 0) g_bsum[blockIdx.x] = carry;
    gbar();
    if (blockIdx.x == 0) {
        int v = ((int)threadIdx.x < (int)gridDim.x) ? g_bsum[threadIdx.x] : 0;
        int tot; int incl = block_scan_incl(v, &tot, swarp);
        if ((int)threadIdx.x < (int)gridDim.x) g_bsum[threadIdx.x] = incl - v;
    }
    gbar();
    {
        int off = g_bsum[blockIdx.x];
        for (int i = base + threadIdx.x; i < lim; i += 1024) {
            int p = g_ptr[i] + off; g_ptr[i] = p; g_cur[i] = p;
        }
    }
    gbar();
    for (int e = gtid; e < N_EV; e += gs) {
        int d = __ldg(etv_e + e);
        g_csr[atomicAdd(&g_cur[d], 1)] = __ldg(etv_v + e);
    }
    for (int e = gtid; e < N_FE; e += gs) {
        int d = NE + __ldg(fte_f + e);
        g_csr[atomicAdd(&g_cur[d], 1)] = __ldg(fte_e + e);
    }
    for (int e = gtid; e < N_FF; e += gs) {
        int d = NE + NF + __ldg(ftf_dst + e);
        g_csr[atomicAdd(&g_cur[d], 1)] = __ldg(ftf_src + e);
    }
}

// ---------------- embeddings: ONE kernel, warp per 4 rows, block-range dispatch ----------------
template<int CIN>
__device__ __forceinline__ void embed_body(
    const float* __restrict__ in, const float* __restrict__ Wt,
    const float* __restrict__ bias, float* __restrict__ out, int n, int blk,
    u64* sW2, u64* sB2)
{
    for (int i = threadIdx.x; i < CIN * 64; i += 256) sW2[i] = *(const u64*)(Wt + 2 * i);
    if (threadIdx.x < 64) sB2[threadIdx.x] = *(const u64*)(bias + 2 * threadIdx.x);
    __syncthreads();
    int w4 = (blk * 8 + (threadIdx.x >> 5)) * 4;
    if (w4 >= n) return;
    int lane = threadIdx.x & 31;
    float x0 = 0.f, x1 = 0.f;
    {
        long long b = (long long)w4 * CIN;
        long long tot = (long long)n * CIN;
        if (lane < 4 * CIN && b + lane < tot) x0 = __ldg(in + b + lane);
        if (32 + lane < 4 * CIN && b + 32 + lane < tot) x1 = __ldg(in + b + 32 + lane);
    }
    u64 a[4][2];
#pragma unroll
    for (int r = 0; r < 4; r++) { a[r][0] = sB2[2 * lane]; a[r][1] = sB2[2 * lane + 1]; }
#pragma unroll
    for (int k = 0; k < CIN; k++) {
        u64 w0 = sW2[k * 64 + 2 * lane], w1 = sW2[k * 64 + 2 * lane + 1];
#pragma unroll
        for (int r = 0; r < 4; r++) {
            int p = r * CIN + k;
            float xk = (p < 32) ? __shfl_sync(~0u, x0, p) : __shfl_sync(~0u, x1, p - 32);
            u64 h2 = pk2(xk, xk);
            a[r][0] = ffma2(h2, w0, a[r][0]);
            a[r][1] = ffma2(h2, w1, a[r][1]);
        }
    }
#pragma unroll
    for (int r = 0; r < 4; r++) {
        int row = w4 + r;
        if (row < n) {
            float2 v0 = upk2(a[r][0]), v1 = upk2(a[r][1]);
            float4 o;
            o.x = v0.x > 0.f ? v0.x : 0.01f * v0.x;
            o.y = v0.y > 0.f ? v0.y : 0.01f * v0.y;
            o.z = v1.x > 0.f ? v1.x : 0.01f * v1.x;
            o.w = v1.y > 0.f ? v1.y : 0.01f * v1.y;
            *(float4*)(out + (size_t)row * WD + lane * 4) = o;
        }
    }
}

#define NB_E 6250   // NE/32
#define NB_V 3125   // NV/32
#define NB_F 3125   // NF/32

__global__ void __launch_bounds__(256)
embed_all(const float* __restrict__ vertices, const float* __restrict__ edges,
          const float* __restrict__ faces,
          const float* __restrict__ Wv, const float* __restrict__ bv,
          const float* __restrict__ We, const float* __restrict__ be,
          const float* __restrict__ Wf, const float* __restrict__ bf,
          float* __restrict__ xv, float* __restrict__ xe, float* __restrict__ xf)
{
    __shared__ u64 sW2[14 * 64];
    __shared__ u64 sB2[64];
    int b = blockIdx.x;
    if (b < NB_E) {
        embed_body<12>(edges, We, be, xe, NE, b, sW2, sB2);
    } else if (b < NB_E + NB_V) {
        embed_body<3>(vertices, Wv, bv, xv, NV, b - NB_E, sW2, sB2);
    } else {
        embed_body<14>(faces, Wf, bf, xf, NF, b - NB_E - NB_V, sW2, sB2);
    }
}

// ---------------- segment min -> maxes (fp-exact transform of segment-max-of-diff) ----------------
__global__ void segmin_kernel(const float* __restrict__ xsrc, const float* __restrict__ xdst,
                              const int* __restrict__ ptr, const int* __restrict__ cnt,
                              const int* __restrict__ csr, float* __restrict__ out, int ndst)
{
    int w = (blockIdx.x * blockDim.x + threadIdx.x) >> 5;
    if (w >= ndst) return;
    int lane = threadIdx.x & 31;
    int deg = __ldg(cnt + w), base = __ldg(ptr + w);
    const float inf = __int_as_float(0x7f800000);
    float4 mn = make_float4(inf, inf, inf, inf);
    int i = 0;
    for (; i + 4 <= deg; i += 4) {
        int s0 = __ldg(csr + base + i), s1 = __ldg(csr + base + i + 1);
        int s2 = __ldg(csr + base + i + 2), s3 = __ldg(csr + base + i + 3);
        float4 v0 = __ldg((const float4*)(xsrc + (size_t)s0 * WD) + lane);
        float4 v1 = __ldg((const float4*)(xsrc + (size_t)s1 * WD) + lane);
        float4 v2 = __ldg((const float4*)(xsrc + (size_t)s2 * WD) + lane);
        float4 v3 = __ldg((const float4*)(xsrc + (size_t)s3 * WD) + lane);
        mn.x = fminf(mn.x, fminf(fminf(v0.x, v1.x), fminf(v2.x, v3.x)));
        mn.y = fminf(mn.y, fminf(fminf(v0.y, v1.y), fminf(v2.y, v3.y)));
        mn.z = fminf(mn.z, fminf(fminf(v0.z, v1.z), fminf(v2.z, v3.z)));
        mn.w = fminf(mn.w, fminf(fminf(v0.w, v1.w), fminf(v2.w, v3.w)));
    }
    for (; i < deg; i++) {
        int s = __ldg(csr + base + i);
        float4 v = __ldg((const float4*)(xsrc + (size_t)s * WD) + lane);
        mn.x = fminf(mn.x, v.x); mn.y = fminf(mn.y, v.y);
        mn.z = fminf(mn.z, v.z); mn.w = fminf(mn.w, v.w);
    }
    float4 o = make_float4(0.f, 0.f, 0.f, 0.f);
    if (deg > 0) {
        float4 a = __ldg((const float4*)(xdst + (size_t)w * WD) + lane);
        o = make_float4(a.x - mn.x, a.y - mn.y, a.z - mn.z, a.w - mn.w);
    }
    ((float4*)(out + (size_t)w * WD))[lane] = o;
}

// ---------------- persistent conv GEMM ----------------
// out = xdst + lrelu([xdst | maxes] @ Wm + bm). W RESIDENT (128KB), h double-buffered,
// pipeline across tile boundaries, persistent grid 148.
// Thread owns col QUADS {cgp+8j}: W fetched as ulonglong2 (LDS.128, 2 pairs/load).
#define CONV_THREADS 256
#define TILE_R 128
#define HSTR 68
#define WFULL (256 * WD)
#define SB_OFF WFULL
#define SH_OFF (WFULL + WD)
#define CONV_SMEM ((SH_OFF + 2 * TILE_R * HSTR) * 4)   // 201216 B

__device__ __forceinline__ void conv_issue_chunk(
    unsigned sHa, const float* xdst, const float* maxbuf, int tile, int c, int n, int tid)
{
    const char* src = (const char*)(c < 2 ? xdst : maxbuf) + (c & 1) * 256;
    unsigned hb = sHa + ((c & 1) * TILE_R * HSTR) * 4;
    int row0 = tile * TILE_R;
#pragma unroll
    for (int t = 0; t < 8; t++) {
        int idx = tid + t * 256;
        int row = idx >> 4, u = idx & 15;
        int sz = (row0 + row < n) ? 16 : 0;
        cp16(hb + row * HSTR * 4 + u * 16, src + (size_t)(row0 + row) * 512 + u * 16, sz);
    }
}

__global__ void __launch_bounds__(CONV_THREADS, 1)
conv_pers(const float* __restrict__ xdst, const float* __restrict__ maxbuf,
          const float* __restrict__ Wm, const float* __restrict__ bm,
          float* __restrict__ out, int n, int ntiles)
{
    extern __shared__ float smem[];
    float* sB = smem + SB_OFF;
    unsigned sWa = (unsigned)__cvta_generic_to_shared(smem);
    unsigned sHa = (unsigned)__cvta_generic_to_shared(smem + SH_OFF);

    int tid = threadIdx.x;
    int bid = blockIdx.x, stride = gridDim.x;
    if (bid >= ntiles) return;

    {
        const char* wsrc = (const char*)Wm;
#pragma unroll
        for (int t = 0; t < 32; t++) {
            int u = tid + t * 256;
            cp16(sWa + u * 16, wsrc + u * 16, 16);
        }
        conv_issue_chunk(sHa, xdst, maxbuf, bid, 0, n, tid);
        CP_COMMIT();
        conv_issue_chunk(sHa, xdst, maxbuf, bid, 1, n, tid);
        CP_COMMIT();
    }
    if (tid < WD) sB[tid] = bm[tid];

    int rg = tid >> 3;      // rows rg*4 .. rg*4+3
    int cgp = tid & 7;      // quad slots: quads cgp+8j, j=0..3; pair idx = 2*(cgp+8j)+i
    const u64* sB2 = (const u64*)sB;
    u64 acc[4][8];          // acc[r][2j+i] = pair 2*(cgp+8j)+i

#pragma unroll 1
    for (int t = bid; t < ntiles; t += stride) {
#pragma unroll 1
        for (int c = 0; c < 4; c++) {
            CP_WAIT1();
            __syncthreads();
            if (c == 0) {
#pragma unroll
                for (int j = 0; j < 4; j++) {
                    u64 b0 = sB2[2 * (cgp + 8 * j)];
                    u64 b1 = sB2[2 * (cgp + 8 * j) + 1];
#pragma unroll
                    for (int r = 0; r < 4; r++) { acc[r][2 * j] = b0; acc[r][2 * j + 1] = b1; }
                }
            }
            const u64* sWc = (const u64*)(smem + c * 8192);      // W rows c*64.. as pairs [64][64]
            const float* hb = smem + SH_OFF + (c & 1) * TILE_R * HSTR + (rg * 4) * HSTR;
#pragma unroll 1
            for (int k4 = 0; k4 < 16; k4++) {
                float4 h4[4];
#pragma unroll
                for (int r = 0; r < 4; r++) h4[r] = *(const float4*)(hb + r * HSTR + k4 * 4);
#pragma unroll
                for (int kk = 0; kk < 4; kk++) {
                    const u64* wr = sWc + (k4 * 4 + kk) * 64;
                    u64 w[8];
#pragma unroll
                    for (int j = 0; j < 4; j++) {
                        ulonglong2 wv = *(const ulonglong2*)(wr + 2 * (cgp + 8 * j));
                        w[2 * j] = wv.x; w[2 * j + 1] = wv.y;
                    }
#pragma unroll
                    for (int r = 0; r < 4; r++) {
                        float hv = (kk == 0) ? h4[r].x : (kk == 1) ? h4[r].y
                                 : (kk == 2) ? h4[r].z : h4[r].w;
                        u64 h2 = pk2(hv, hv);
#pragma unroll
                        for (int cc = 0; cc < 8; cc++) acc[r][cc] = ffma2(h2, w[cc], acc[r][cc]);
                    }
                }
            }
            __syncthreads();
            int tn = (c < 2) ? t : t + stride;
            int cn = (c < 2) ? c + 2 : c - 2;
            if (tn < ntiles) conv_issue_chunk(sHa, xdst, maxbuf, tn, cn, n, tid);
            CP_COMMIT();
        }
        // epilogue: lrelu + residual, direct coalesced float2 ld/st
        int row0 = t * TILE_R;
#pragma unroll
        for (int r = 0; r < 4; r++) {
            int grow = row0 + rg * 4 + r;
            if (grow < n) {
                const float* xrow = xdst + (size_t)grow * WD;
                float* orow = out + (size_t)grow * WD;
#pragma unroll
                for (int j = 0; j < 4; j++) {
#pragma unroll
                    for (int i2 = 0; i2 < 2; i2++) {
                        int c0 = 2 * (2 * (cgp + 8 * j) + i2);
                        float2 v = upk2(acc[r][2 * j + i2]);
                        float a0 = v.x > 0.f ? v.x : 0.01f * v.x;
                        float a1 = v.y > 0.f ? v.y : 0.01f * v.y;
                        float2 x = __ldg((const float2*)(xrow + c0));
                        float2 res; res.x = x.x + a0; res.y = x.y + a1;
                        *(float2*)(orow + c0) = res;
                    }
                }
            }
        }
    }
}

// ---------------- launch ----------------
extern "C" void kernel_launch(void* const* d_in, const int* in_sizes, int n_in,
                              void* d_out, int out_size)
{
    const float* vertices = (const float*)d_in[0];
    const float* edges    = (const float*)d_in[1];
    const float* faces    = (const float*)d_in[2];
    const int* etv_v   = (const int*)d_in[3];
    const int* etv_e   = (const int*)d_in[4];
    const int* fte_e   = (const int*)d_in[5];
    const int* fte_f   = (const int*)d_in[6];
    const int* ftf_src = (const int*)d_in[7];
    const int* ftf_dst = (const int*)d_in[8];
    const float* Wv   = (const float*)d_in[9];
    const float* bv   = (const float*)d_in[10];
    const float* We   = (const float*)d_in[11];
    const float* be   = (const float*)d_in[12];
    const float* Wf   = (const float*)d_in[13];
    const float* bf   = (const float*)d_in[14];
    const float* Wv2e = (const float*)d_in[15];
    const float* bv2e = (const float*)d_in[16];
    const float* We2f = (const float*)d_in[17];
    const float* be2f = (const float*)d_in[18];
    const float* Wm0  = (const float*)d_in[19];
    const float* bm0  = (const float*)d_in[20];
    const float* Wm1  = (const float*)d_in[21];
    const float* bm1  = (const float*)d_in[22];

    float *xv, *xe, *mx;
    int *cnt, *ptr, *csr;
    cudaGetSymbolAddress((void**)&xv, g_xv);
    cudaGetSymbolAddress((void**)&xe, g_xe);
    cudaGetSymbolAddress((void**)&mx, g_max);
    cudaGetSymbolAddress((void**)&cnt, g_cnt);
    cudaGetSymbolAddress((void**)&ptr, g_ptr);
    cudaGetSymbolAddress((void**)&csr, g_csr);
    float* xf = (float*)d_out;

    cudaFuncSetAttribute(conv_pers, cudaFuncAttributeMaxDynamicSharedMemorySize, CONV_SMEM);

    const int NT_E = (NE + TILE_R - 1) / TILE_R;   // 1563
    const int NT_F = (NF + TILE_R - 1) / TILE_R;   // 782

    // 0: all 3 CSRs (index-only)
    build_csr_all<<<148, 1024>>>(etv_v, etv_e, fte_e, fte_f, ftf_src, ftf_dst);

    // 1: all 3 embeddings in one kernel
    embed_all<<<NB_E + NB_V + NB_F, 256>>>(vertices, edges, faces,
                                           Wv, bv, We, be, Wf, bf, xv, xe, xf);

    // V2E
    segmin_kernel<<<(NE + 7) / 8, 256>>>(xv, xe, ptr, cnt, csr, mx, NE);
    conv_pers<<<148, CONV_THREADS, CONV_SMEM>>>(xe, mx, Wv2e, bv2e, xe, NE, NT_E);

    // E2F
    segmin_kernel<<<(NF + 7) / 8, 256>>>(xe, xf, ptr + NE, cnt + NE, csr, mx, NF);
    conv_pers<<<148, CONV_THREADS, CONV_SMEM>>>(xf, mx, We2f, be2f, xf, NF, NT_F);

    // FF layer 0 (ftf CSR reused)
    segmin_kernel<<<(NF + 7) / 8, 256>>>(xf, xf, ptr + NE + NF, cnt + NE + NF, csr, mx, NF);
    conv_pers<<<148, CONV_THREADS, CONV_SMEM>>>(xf, mx, Wm0, bm0, xf, NF, NT_F);

    // FF layer 1
    segmin_kernel<<<(NF + 7) / 8, 256>>>(xf, xf, ptr + NE + NF, cnt + NE + NF, csr, mx, NF);
    conv_pers<<<148, CONV_THREADS, CONV_SMEM>>>(xf, mx, Wm1, bm1, xf, NF, NT_F);
}